// round 6
// baseline (speedup 1.0000x reference)
#include <cuda_runtime.h>
#include <cuda_bf16.h>

// TrajectoryScore: segmented streaming reduction, single fused kernel.
// 64 segments x 100k obs; 24B read per obs -> 153.6MB. Memory-bound.
//
// - Warp-tile of 128 obs (= 96 float4 per array): 3+3 perfectly coalesced
//   LDG.128 per lane, diffs staged in 16B-aligned smem (conflict-free
//   48B-stride LDS.128 readback), then mixture-model math w/ fast intrinsics.
// - Block reduce -> per-block partials in __device__ scratch.
// - Last arriving block (threadfence + atomic counter) sums partials in
//   fixed order and writes the 3*B outputs. Counter self-resets -> graph
//   replay deterministic, no allocations.

#define BPS   8      // blocks per segment
#define NTHR  256    // threads per block
#define NWPB  (NTHR / 32)
#define MAX_B 256

__device__ float    g_partial[MAX_B * BPS * 2];
__device__ unsigned g_count = 0;

__global__ __launch_bounds__(NTHR)
void score_kernel(const float* __restrict__ u_pred,
                  const float* __restrict__ u_obs,
                  const float* __restrict__ h_arr,
                  const float* __restrict__ lam_arr,
                  const float* __restrict__ thr_arr,
                  float* __restrict__ out,
                  int n_per)
{
    const int seg  = blockIdx.y;
    const int wid  = threadIdx.x >> 5;
    const int lane = threadIdx.x & 31;

    // Per-segment constants (uniform across block)
    const float T     = thr_arr[seg];
    const float hh    = h_arr[seg];
    const float lm    = lam_arr[seg];
    const float q     = 1.0f - hh;
    const float c     = hh * lm / (1.0f - __expf(-lm));
    const float scale = -lm / T;   // exp(-lam * s2/T)

    float accL = 0.0f;   // sum log(p) over close obs
    float accH = 0.0f;   // sum p_hit_post over close & real-hit obs

#define DO_OBS(dx, dy, dz)                                              \
    {                                                                   \
        float s2 = (dx) * (dx);                                         \
        s2 = fmaf((dy), (dy), s2);                                      \
        s2 = fmaf((dz), (dz), s2);                                      \
        float e    = __expf(s2 * scale);                                \
        float ph   = c * e;                                             \
        float p    = ph + q;                                            \
        float lp   = __logf(p);                                         \
        float post = __fdividef(ph, p);                                 \
        bool close = s2 < T;                                            \
        accL += close ? lp : 0.0f;                                      \
        accH += (close && post > 0.95f) ? post : 0.0f;                  \
    }

    const long long segf = (long long)seg * (long long)n_per * 3LL;

    // -------- main path: warp tiles of 128 obs (96 float4 per array) -----
    if ((((long long)n_per * 3LL) & 3LL) == 0) {
        const float4* __restrict__ p4 = (const float4*)u_pred + (segf >> 2);
        const float4* __restrict__ o4 = (const float4*)u_obs  + (segf >> 2);

        // float4-typed smem => guaranteed 16B alignment for LDS/STS.128
        __shared__ float4 sdiff4[NWPB * 96];
        float4* sw4 = sdiff4 + wid * 96;
        const float* sw = (const float*)sw4;

        const int ntile = n_per >> 7;            // full 128-obs tiles
        const int wglob = blockIdx.x * NWPB + wid;

        for (int t = wglob; t < ntile; t += BPS * NWPB) {
            const int base = t * 96 + lane;
            float4 a0 = p4[base +  0];
            float4 a1 = p4[base + 32];
            float4 a2 = p4[base + 64];
            float4 b0 = o4[base +  0];
            float4 b1 = o4[base + 32];
            float4 b2 = o4[base + 64];
            float4 d0 = make_float4(a0.x - b0.x, a0.y - b0.y, a0.z - b0.z, a0.w - b0.w);
            float4 d1 = make_float4(a1.x - b1.x, a1.y - b1.y, a1.z - b1.z, a1.w - b1.w);
            float4 d2 = make_float4(a2.x - b2.x, a2.y - b2.y, a2.z - b2.z, a2.w - b2.w);

            sw4[lane +  0] = d0;
            sw4[lane + 32] = d1;
            sw4[lane + 64] = d2;
            __syncwarp();

            // 12 consecutive floats = this lane's 4 obs
            // byte offsets 48*lane {+0,+16,+32}: all 16B-aligned, no conflicts
            float4 e0 = *(const float4*)(sw + 12 * lane + 0);
            float4 e1 = *(const float4*)(sw + 12 * lane + 4);
            float4 e2 = *(const float4*)(sw + 12 * lane + 8);
            __syncwarp();

            DO_OBS(e0.x, e0.y, e0.z);
            DO_OBS(e0.w, e1.x, e1.y);
            DO_OBS(e1.z, e1.w, e2.x);
            DO_OBS(e2.y, e2.z, e2.w);
        }

        // tail obs (n_per % 128), scalar, chunk 0 only
        if (blockIdx.x == 0) {
            for (int i = (ntile << 7) + threadIdx.x; i < n_per; i += NTHR) {
                const float* pp = u_pred + segf + 3LL * i;
                const float* oo = u_obs  + segf + 3LL * i;
                DO_OBS(pp[0] - oo[0], pp[1] - oo[1], pp[2] - oo[2]);
            }
        }
    } else {
        // generic scalar fallback (not hit for this shape)
        for (int i = blockIdx.x * NTHR + threadIdx.x; i < n_per;
             i += BPS * NTHR) {
            const float* pp = u_pred + segf + 3LL * i;
            const float* oo = u_obs  + segf + 3LL * i;
            DO_OBS(pp[0] - oo[0], pp[1] - oo[1], pp[2] - oo[2]);
        }
    }
#undef DO_OBS

    // -------- block reduction --------
    #pragma unroll
    for (int o = 16; o > 0; o >>= 1) {
        accL += __shfl_down_sync(0xffffffffu, accL, o);
        accH += __shfl_down_sync(0xffffffffu, accH, o);
    }

    __shared__ float sL[NWPB];
    __shared__ float sH[NWPB];
    if (lane == 0) { sL[wid] = accL; sH[wid] = accH; }
    __syncthreads();

    if (wid == 0) {
        accL = (lane < NWPB) ? sL[lane] : 0.0f;
        accH = (lane < NWPB) ? sH[lane] : 0.0f;
        #pragma unroll
        for (int o = NWPB / 2; o > 0; o >>= 1) {
            accL += __shfl_down_sync(0xffffffffu, accL, o);
            accH += __shfl_down_sync(0xffffffffu, accH, o);
        }
        if (lane == 0) {
            const int idx = (seg * BPS + blockIdx.x) * 2;
            g_partial[idx + 0] = accL;
            g_partial[idx + 1] = accH;
        }
    }

    // -------- last-block final reduction (deterministic fixed order) -----
    __shared__ bool isLast;
    if (threadIdx.x == 0) {
        __threadfence();
        unsigned v = atomicAdd(&g_count, 1u);
        isLast = (v == gridDim.x * gridDim.y - 1);
    }
    __syncthreads();

    if (isLast) {
        __threadfence();
        const int B = gridDim.y;
        for (int j = threadIdx.x; j < B; j += NTHR) {
            float fL = 0.0f, fH = 0.0f;
            #pragma unroll
            for (int b = 0; b < BPS; b++) {
                fL += g_partial[(j * BPS + b) * 2 + 0];
                fH += g_partial[(j * BPS + b) * 2 + 1];
            }
            out[j]         = fL;   // log_like
            out[B + j]     = fH;   // hits
            out[2 * B + j] = fH;   // hits_raw
        }
        if (threadIdx.x == 0) g_count = 0;   // reset for next graph replay
    }
}

extern "C" void kernel_launch(void* const* d_in, const int* in_sizes, int n_in,
                              void* d_out, int out_size)
{
    const float* u_pred = (const float*)d_in[0];
    const float* u_obs  = (const float*)d_in[1];
    const float* h      = (const float*)d_in[2];
    const float* lam    = (const float*)d_in[3];
    const float* thr    = (const float*)d_in[4];
    float* out = (float*)d_out;

    const int B = out_size / 3;
    long long e0 = in_sizes[0];
    long long N = (e0 % 3 == 0) ? (e0 / 3) : e0;
    const int n_per = (int)(N / B);

    dim3 grid(BPS, B);
    score_kernel<<<grid, NTHR>>>(u_pred, u_obs, h, lam, thr, out, n_per);
}